// round 12
// baseline (speedup 1.0000x reference)
#include <cuda_runtime.h>
#include <cuda_bf16.h>

// EdgeAtt: B=64, L=512, D=512. PDL + self-cleaning per-batch flags:
// k_soft CTAs of batch b proceed once k_proj's 64 CTAs of batch b signal.
// Flags: low 16 bits = producer count, high bits = consumer count; the
// 64th consumer resets the word -> no reset kernel, graph-replay safe.

#define L_DIM 512
#define D_DIM 512
#define SLOPE 0.2f
#define MASKV -1e9f

__device__ float        g_ei[64 * L_DIM];
__device__ float        g_ej[64 * L_DIM];
__device__ unsigned int g_flag[64];   // static init = 0; self-cleaning thereafter

// ---------------- kernel 1: dual projection, warp per row ----------------
__global__ void __launch_bounds__(256) k_proj(const float* __restrict__ nf,
                                              const float* __restrict__ wa,
                                              const int* __restrict__ tlen) {
    cudaTriggerProgrammaticLaunchCompletion();   // let k_soft start dispatching

    const int tid  = threadIdx.x;
    const int warp = tid >> 5;
    const int lane = tid & 31;
    const int r    = blockIdx.x * 8 + warp;      // global row
    const int b    = r >> 9;
    const int l    = r & (L_DIM - 1);
    const int len  = __ldg(&tlen[b]);

    if (l < len) {                               // unused projections skipped
        const float4* row = reinterpret_cast<const float4*>(nf + (size_t)r * D_DIM);
        const float4* w1  = reinterpret_cast<const float4*>(wa);
        const float4* w2  = reinterpret_cast<const float4*>(wa + D_DIM);

        float s1 = 0.f, s2 = 0.f;
#pragma unroll
        for (int t = 0; t < 4; t++) {
            int idx = lane + t * 32;
            float4 v = row[idx];
            float4 a = __ldg(&w1[idx]);
            float4 w = __ldg(&w2[idx]);
            s1 += v.x * a.x + v.y * a.y + v.z * a.z + v.w * a.w;
            s2 += v.x * w.x + v.y * w.y + v.z * w.z + v.w * w.w;
        }
#pragma unroll
        for (int o = 16; o; o >>= 1) {
            s1 += __shfl_xor_sync(0xffffffffu, s1, o);
            s2 += __shfl_xor_sync(0xffffffffu, s2, o);
        }
        if (lane == 0) { g_ei[r] = s1; g_ej[r] = s2; }
    }

    // release: cta-sync chains all warps' writes into tid0's gpu-scope release
    __syncthreads();
    if (tid == 0) {
        __threadfence();
        atomicAdd(&g_flag[b], 1u);               // producer count (low bits)
    }
}

// consumer bookkeeping: count in high bits; 64th consumer resets the flag
__device__ __forceinline__ void consume_flag(int b) {
    unsigned int old = atomicAdd(&g_flag[b], 0x10000u);
    if ((old >> 16) == 63u) {                    // we are the last consumer
        atomicExch(&g_flag[b], 0u);              // reset for next replay
    }
}

// ---------------- kernel 2: masked softmax, warp per output row ----------------
__global__ void __launch_bounds__(256) k_soft(const float* __restrict__ ba,
                                              const int* __restrict__ tlen,
                                              float* __restrict__ out) {
    __shared__ float sej[L_DIM];
    __shared__ float smax[8];

    const int b    = blockIdx.y;
    const int tid  = threadIdx.x;
    const int warp = tid >> 5;
    const int lane = tid & 31;
    const int len  = __ldg(&tlen[b]);            // input only: no dependency
    const int i    = blockIdx.x * 8 + warp;

    float4* orow4 = reinterpret_cast<float4*>(out + ((size_t)b * L_DIM + i) * L_DIM);

    // ---- independent prologue: zero rows (overlaps k_proj) ----
    if (i >= len) {
        float4 z = make_float4(0.f, 0.f, 0.f, 0.f);
#pragma unroll
        for (int t = 0; t < 4; t++) orow4[t * 32 + lane] = z;
        if (blockIdx.x * 8 >= len) {             // whole CTA invalid: no wait
            __syncthreads();
            if (tid == 0) consume_flag(b);
            return;
        }
    }

    // ---- per-batch acquire: wait only for this batch's 64 producers ----
    if (tid == 0) {
        unsigned int v;
        do {
            asm volatile("ld.global.acquire.gpu.b32 %0, [%1];"
                         : "=r"(v) : "l"(&g_flag[b]) : "memory");
        } while ((v & 0xFFFFu) < 64u);
        consume_flag(b);
    }
    __syncthreads();

    // premasked e_j: j>=len -> -1e9 (exp underflows to exact 0)
    const float v0 = (tid       < len) ? g_ej[b * L_DIM + tid]       : MASKV;
    const float v1 = (tid + 256 < len) ? g_ej[b * L_DIM + tid + 256] : MASKV;
    sej[tid]       = v0;
    sej[tid + 256] = v1;

    // block max of premasked e_j (len >= 1)
    float mv = fmaxf(v0, v1);
#pragma unroll
    for (int o = 16; o; o >>= 1) mv = fmaxf(mv, __shfl_xor_sync(0xffffffffu, mv, o));
    if (lane == 0) smax[warp] = mv;
    __syncthreads();
    float mxej = smax[0];
#pragma unroll
    for (int k = 1; k < 8; k++) mxej = fmaxf(mxej, smax[k]);

    if (i >= len) return;                        // zero row already written

    const float ei   = g_ei[b * L_DIM + i] + __ldg(ba);
    const float mraw = ei + mxej;
    const float m    = fmaxf(mraw, SLOPE * mraw);   // exact row max (monotonic lrelu)

    float4 p[4];
    float s = 0.f;
#pragma unroll
    for (int t = 0; t < 4; t++) {
        const int j0 = t * 128 + lane * 4;
        float4 e4 = *reinterpret_cast<const float4*>(&sej[j0]);

        float v, lr, pe;
        v = ei + e4.x; lr = fmaxf(v, SLOPE * v);
        pe = __expf(lr - m); p[t].x = pe; s += pe;
        v = ei + e4.y; lr = fmaxf(v, SLOPE * v);
        pe = __expf(lr - m); p[t].y = pe; s += pe;
        v = ei + e4.z; lr = fmaxf(v, SLOPE * v);
        pe = __expf(lr - m); p[t].z = pe; s += pe;
        v = ei + e4.w; lr = fmaxf(v, SLOPE * v);
        pe = __expf(lr - m); p[t].w = pe; s += pe;
    }
#pragma unroll
    for (int o = 16; o; o >>= 1) s += __shfl_xor_sync(0xffffffffu, s, o);

    const float inv = 1.f / s;
#pragma unroll
    for (int t = 0; t < 4; t++) {
        float4 r;
        r.x = p[t].x * inv; r.y = p[t].y * inv;
        r.z = p[t].z * inv; r.w = p[t].w * inv;
        orow4[t * 32 + lane] = r;
    }
}

extern "C" void kernel_launch(void* const* d_in, const int* in_sizes, int n_in,
                              void* d_out, int out_size) {
    const float* nf   = (const float*)d_in[0];   // [B, L, D]
    const float* wa   = (const float*)d_in[1];   // [2D]
    const float* ba   = (const float*)d_in[2];   // [1]
    const int*   tlen = (const int*)d_in[3];     // [B]
    float* out = (float*)d_out;                  // [B, L, L]

    const int B = in_sizes[3];

    k_proj<<<B * L_DIM / 8, 256>>>(nf, wa, tlen);

    // PDL: k_soft dispatches while k_proj runs; per-batch flags gate the
    // actual data dependency (no grid-wide sync needed).
    cudaLaunchConfig_t cfg = {};
    cfg.gridDim  = dim3(L_DIM / 8, (unsigned)B, 1);
    cfg.blockDim = dim3(256, 1, 1);
    cfg.dynamicSmemBytes = 0;
    cfg.stream = 0;
    cudaLaunchAttribute attr[1];
    attr[0].id = cudaLaunchAttributeProgrammaticStreamSerialization;
    attr[0].val.programmaticStreamSerializationAllowed = 1;
    cfg.attrs = attr;
    cfg.numAttrs = 1;
    cudaLaunchKernelEx(&cfg, k_soft, ba, tlen, out);
}

// round 13
// speedup vs baseline: 1.1736x; 1.1736x over previous
#include <cuda_runtime.h>
#include <cuda_bf16.h>

// EdgeAtt: B=64, L=512, D=512.
// k_proj: warp per row; valid rows (l<len) do the dual projection (DRAM
// reads), invalid rows (l>=len) write their zero output row (L2 stores) —
// the two streams overlap inside one kernel. k_soft: valid rows only.

#define L_DIM 512
#define D_DIM 512
#define SLOPE 0.2f
#define MASKV -1e9f

__device__ float g_ei[64 * L_DIM];
__device__ float g_ej[64 * L_DIM];

// ---------------- kernel 1: projection + zero rows ----------------
__global__ void __launch_bounds__(256) k_proj(const float* __restrict__ nf,
                                              const float* __restrict__ wa,
                                              const int* __restrict__ tlen,
                                              float* __restrict__ out) {
    cudaTriggerProgrammaticLaunchCompletion();

    const int tid  = threadIdx.x;
    const int warp = tid >> 5;
    const int lane = tid & 31;
    const int r    = blockIdx.x * 8 + warp;      // global row
    const int b    = r >> 9;
    const int l    = r & (L_DIM - 1);
    const int len  = __ldg(&tlen[b]);

    if (l < len) {
        // dual projection (DRAM read stream)
        const float4* row = reinterpret_cast<const float4*>(nf + (size_t)r * D_DIM);
        const float4* w1  = reinterpret_cast<const float4*>(wa);
        const float4* w2  = reinterpret_cast<const float4*>(wa + D_DIM);

        float s1 = 0.f, s2 = 0.f;
#pragma unroll
        for (int t = 0; t < 4; t++) {
            int idx = lane + t * 32;
            float4 v = row[idx];
            float4 a = __ldg(&w1[idx]);
            float4 w = __ldg(&w2[idx]);
            s1 += v.x * a.x + v.y * a.y + v.z * a.z + v.w * a.w;
            s2 += v.x * w.x + v.y * w.y + v.z * w.z + v.w * w.w;
        }
#pragma unroll
        for (int o = 16; o; o >>= 1) {
            s1 += __shfl_xor_sync(0xffffffffu, s1, o);
            s2 += __shfl_xor_sync(0xffffffffu, s2, o);
        }
        if (lane == 0) { g_ei[r] = s1; g_ej[r] = s2; }
    } else {
        // zero output row i = l of batch b (L2 store stream, overlaps reads)
        float4* orow4 = reinterpret_cast<float4*>(out + (size_t)r * L_DIM);
        float4 z = make_float4(0.f, 0.f, 0.f, 0.f);
#pragma unroll
        for (int t = 0; t < 4; t++) orow4[t * 32 + lane] = z;
    }
}

// ---------------- kernel 2: masked softmax, valid rows only ----------------
__global__ void __launch_bounds__(256) k_soft(const float* __restrict__ ba,
                                              const int* __restrict__ tlen,
                                              float* __restrict__ out) {
    __shared__ float sej[L_DIM];
    __shared__ float smax[8];

    const int b    = blockIdx.y;
    const int tid  = threadIdx.x;
    const int warp = tid >> 5;
    const int lane = tid & 31;
    const int len  = __ldg(&tlen[b]);            // input only: no dependency

    // whole CTA invalid: zeros already written by k_proj, nothing to do
    if (blockIdx.x * 8 >= len) return;           // exit implies PDL sync

    cudaGridDependencySynchronize();

    // premasked e_j: j>=len -> -1e9 (exp underflows to exact 0)
    const float v0 = (tid       < len) ? g_ej[b * L_DIM + tid]       : MASKV;
    const float v1 = (tid + 256 < len) ? g_ej[b * L_DIM + tid + 256] : MASKV;
    sej[tid]       = v0;
    sej[tid + 256] = v1;

    // block max of premasked e_j (len >= 1)
    float mv = fmaxf(v0, v1);
#pragma unroll
    for (int o = 16; o; o >>= 1) mv = fmaxf(mv, __shfl_xor_sync(0xffffffffu, mv, o));
    if (lane == 0) smax[warp] = mv;
    __syncthreads();
    float mxej = smax[0];
#pragma unroll
    for (int k = 1; k < 8; k++) mxej = fmaxf(mxej, smax[k]);

    const int i = blockIdx.x * 8 + warp;
    if (i >= len) return;                        // zero row already written

    float4* orow4 = reinterpret_cast<float4*>(out + ((size_t)b * L_DIM + i) * L_DIM);

    const float ei   = g_ei[b * L_DIM + i] + __ldg(ba);
    const float mraw = ei + mxej;
    const float m    = fmaxf(mraw, SLOPE * mraw);   // exact row max (monotonic lrelu)

    float4 p[4];
    float s = 0.f;
#pragma unroll
    for (int t = 0; t < 4; t++) {
        const int j0 = t * 128 + lane * 4;
        float4 e4 = *reinterpret_cast<const float4*>(&sej[j0]);

        float v, lr, pe;
        v = ei + e4.x; lr = fmaxf(v, SLOPE * v);
        pe = __expf(lr - m); p[t].x = pe; s += pe;
        v = ei + e4.y; lr = fmaxf(v, SLOPE * v);
        pe = __expf(lr - m); p[t].y = pe; s += pe;
        v = ei + e4.z; lr = fmaxf(v, SLOPE * v);
        pe = __expf(lr - m); p[t].z = pe; s += pe;
        v = ei + e4.w; lr = fmaxf(v, SLOPE * v);
        pe = __expf(lr - m); p[t].w = pe; s += pe;
    }
#pragma unroll
    for (int o = 16; o; o >>= 1) s += __shfl_xor_sync(0xffffffffu, s, o);

    const float inv = 1.f / s;
#pragma unroll
    for (int t = 0; t < 4; t++) {
        float4 r;
        r.x = p[t].x * inv; r.y = p[t].y * inv;
        r.z = p[t].z * inv; r.w = p[t].w * inv;
        orow4[t * 32 + lane] = r;
    }
}

extern "C" void kernel_launch(void* const* d_in, const int* in_sizes, int n_in,
                              void* d_out, int out_size) {
    const float* nf   = (const float*)d_in[0];   // [B, L, D]
    const float* wa   = (const float*)d_in[1];   // [2D]
    const float* ba   = (const float*)d_in[2];   // [1]
    const int*   tlen = (const int*)d_in[3];     // [B]
    float* out = (float*)d_out;                  // [B, L, L]

    const int B = in_sizes[3];

    k_proj<<<B * L_DIM / 8, 256>>>(nf, wa, tlen, out);

    cudaLaunchConfig_t cfg = {};
    cfg.gridDim  = dim3(L_DIM / 8, (unsigned)B, 1);
    cfg.blockDim = dim3(256, 1, 1);
    cfg.dynamicSmemBytes = 0;
    cfg.stream = 0;
    cudaLaunchAttribute attr[1];
    attr[0].id = cudaLaunchAttributeProgrammaticStreamSerialization;
    attr[0].val.programmaticStreamSerializationAllowed = 1;
    cfg.attrs = attr;
    cfg.numAttrs = 1;
    cudaLaunchKernelEx(&cfg, k_soft, ba, tlen, out);
}

// round 14
// speedup vs baseline: 1.1913x; 1.0151x over previous
#include <cuda_runtime.h>
#include <cuda_bf16.h>

// EdgeAtt: B=64, L=512, D=512.
// k_proj: warp/row; valid rows project (DRAM reads), invalid rows write
// their zero output row (L2 stores) — streams overlap in one kernel.
// k_soft: valid rows only, dynamic column skip (tiles >= len store zeros
// without computing exp).

#define L_DIM 512
#define D_DIM 512
#define SLOPE 0.2f
#define MASKV -1e9f

__device__ float g_ei[64 * L_DIM];
__device__ float g_ej[64 * L_DIM];

// ---------------- kernel 1: projection + zero rows ----------------
__global__ void __launch_bounds__(256) k_proj(const float* __restrict__ nf,
                                              const float* __restrict__ wa,
                                              const int* __restrict__ tlen,
                                              float* __restrict__ out) {
    cudaTriggerProgrammaticLaunchCompletion();

    const int tid  = threadIdx.x;
    const int warp = tid >> 5;
    const int lane = tid & 31;
    const int r    = blockIdx.x * 8 + warp;      // global row
    const int b    = r >> 9;
    const int l    = r & (L_DIM - 1);
    const int len  = __ldg(&tlen[b]);

    if (l < len) {
        const float4* row = reinterpret_cast<const float4*>(nf + (size_t)r * D_DIM);
        const float4* w1  = reinterpret_cast<const float4*>(wa);
        const float4* w2  = reinterpret_cast<const float4*>(wa + D_DIM);

        float s1 = 0.f, s2 = 0.f;
#pragma unroll
        for (int t = 0; t < 4; t++) {
            int idx = lane + t * 32;
            float4 v = row[idx];
            float4 a = __ldg(&w1[idx]);
            float4 w = __ldg(&w2[idx]);
            s1 += v.x * a.x + v.y * a.y + v.z * a.z + v.w * a.w;
            s2 += v.x * w.x + v.y * w.y + v.z * w.z + v.w * w.w;
        }
#pragma unroll
        for (int o = 16; o; o >>= 1) {
            s1 += __shfl_xor_sync(0xffffffffu, s1, o);
            s2 += __shfl_xor_sync(0xffffffffu, s2, o);
        }
        if (lane == 0) { g_ei[r] = s1; g_ej[r] = s2; }
    } else {
        // zero output row (L2 store stream overlaps the read stream)
        float4* orow4 = reinterpret_cast<float4*>(out + (size_t)r * L_DIM);
        float4 z = make_float4(0.f, 0.f, 0.f, 0.f);
#pragma unroll
        for (int t = 0; t < 4; t++) orow4[t * 32 + lane] = z;
    }
}

// ---------------- kernel 2: masked softmax, valid rows, column skip ----------------
__global__ void __launch_bounds__(256) k_soft(const float* __restrict__ ba,
                                              const int* __restrict__ tlen,
                                              float* __restrict__ out) {
    __shared__ float sej[L_DIM];
    __shared__ float smax[8];

    const int b    = blockIdx.y;
    const int tid  = threadIdx.x;
    const int warp = tid >> 5;
    const int lane = tid & 31;
    const int len  = __ldg(&tlen[b]);            // input only: no dependency

    // whole CTA invalid: zeros already written by k_proj
    if (blockIdx.x * 8 >= len) return;

    cudaGridDependencySynchronize();

    // premasked e_j (only the first nt tiles are ever read)
    const float v0 = (tid       < len) ? g_ej[b * L_DIM + tid]       : MASKV;
    const float v1 = (tid + 256 < len) ? g_ej[b * L_DIM + tid + 256] : MASKV;
    sej[tid]       = v0;
    sej[tid + 256] = v1;

    // block max of premasked e_j (len >= 1)
    float mv = fmaxf(v0, v1);
#pragma unroll
    for (int o = 16; o; o >>= 1) mv = fmaxf(mv, __shfl_xor_sync(0xffffffffu, mv, o));
    if (lane == 0) smax[warp] = mv;
    __syncthreads();
    float mxej = smax[0];
#pragma unroll
    for (int k = 1; k < 8; k++) mxej = fmaxf(mxej, smax[k]);

    const int i = blockIdx.x * 8 + warp;
    if (i >= len) return;                        // zero row already written

    float4* orow4 = reinterpret_cast<float4*>(out + ((size_t)b * L_DIM + i) * L_DIM);

    const float ei   = g_ei[b * L_DIM + i] + __ldg(ba);
    const float mraw = ei + mxej;
    const float m    = fmaxf(mraw, SLOPE * mraw);   // exact row max (monotonic lrelu)

    const int nt = (len + 127) >> 7;             // live tiles (1..4), warp-uniform

    float4 p[4];
    float s = 0.f;
#pragma unroll
    for (int t = 0; t < 4; t++) {
        if (t < nt) {
            const int j0 = t * 128 + lane * 4;
            float4 e4 = *reinterpret_cast<const float4*>(&sej[j0]);
            float v, lr, pe;
            v = ei + e4.x; lr = fmaxf(v, SLOPE * v);
            pe = __expf(lr - m); p[t].x = pe; s += pe;
            v = ei + e4.y; lr = fmaxf(v, SLOPE * v);
            pe = __expf(lr - m); p[t].y = pe; s += pe;
            v = ei + e4.z; lr = fmaxf(v, SLOPE * v);
            pe = __expf(lr - m); p[t].z = pe; s += pe;
            v = ei + e4.w; lr = fmaxf(v, SLOPE * v);
            pe = __expf(lr - m); p[t].w = pe; s += pe;
        }
    }
#pragma unroll
    for (int o = 16; o; o >>= 1) s += __shfl_xor_sync(0xffffffffu, s, o);

    const float inv = 1.f / s;
#pragma unroll
    for (int t = 0; t < 4; t++) {
        float4 r;
        if (t < nt) {
            r.x = p[t].x * inv; r.y = p[t].y * inv;
            r.z = p[t].z * inv; r.w = p[t].w * inv;
        } else {
            r = make_float4(0.f, 0.f, 0.f, 0.f);  // dead tile: plain zeros
        }
        orow4[t * 32 + lane] = r;
    }
}

extern "C" void kernel_launch(void* const* d_in, const int* in_sizes, int n_in,
                              void* d_out, int out_size) {
    const float* nf   = (const float*)d_in[0];   // [B, L, D]
    const float* wa   = (const float*)d_in[1];   // [2D]
    const float* ba   = (const float*)d_in[2];   // [1]
    const int*   tlen = (const int*)d_in[3];     // [B]
    float* out = (float*)d_out;                  // [B, L, L]

    const int B = in_sizes[3];

    k_proj<<<B * L_DIM / 8, 256>>>(nf, wa, tlen, out);

    cudaLaunchConfig_t cfg = {};
    cfg.gridDim  = dim3(L_DIM / 8, (unsigned)B, 1);
    cfg.blockDim = dim3(256, 1, 1);
    cfg.dynamicSmemBytes = 0;
    cfg.stream = 0;
    cudaLaunchAttribute attr[1];
    attr[0].id = cudaLaunchAttributeProgrammaticStreamSerialization;
    attr[0].val.programmaticStreamSerializationAllowed = 1;
    cfg.attrs = attr;
    cfg.numAttrs = 1;
    cudaLaunchKernelEx(&cfg, k_soft, ba, tlen, out);
}

// round 15
// speedup vs baseline: 1.2076x; 1.0137x over previous
#include <cuda_runtime.h>
#include <cuda_bf16.h>

// EdgeAtt: B=64, L=512, D=512.
// k_proj: warp/row; valid rows project (DRAM reads), invalid rows write
// their zero output row (L2 stores) — streams overlap in one kernel.
// k_soft: warp-autonomous. Each warp holds all 512 premasked e_j in 16
// registers, computes the batch max itself (no smem, no barriers), and
// emits 4 output rows. Column skip for tiles >= len.

#define L_DIM 512
#define D_DIM 512
#define SLOPE 0.2f
#define MASKV -1e9f

__device__ float g_ei[64 * L_DIM];
__device__ float g_ej[64 * L_DIM];

// ---------------- kernel 1: projection + zero rows ----------------
__global__ void __launch_bounds__(256) k_proj(const float* __restrict__ nf,
                                              const float* __restrict__ wa,
                                              const int* __restrict__ tlen,
                                              float* __restrict__ out) {
    cudaTriggerProgrammaticLaunchCompletion();

    const int tid  = threadIdx.x;
    const int warp = tid >> 5;
    const int lane = tid & 31;
    const int r    = blockIdx.x * 8 + warp;      // global row
    const int b    = r >> 9;
    const int l    = r & (L_DIM - 1);
    const int len  = __ldg(&tlen[b]);

    if (l < len) {
        const float4* row = reinterpret_cast<const float4*>(nf + (size_t)r * D_DIM);
        const float4* w1  = reinterpret_cast<const float4*>(wa);
        const float4* w2  = reinterpret_cast<const float4*>(wa + D_DIM);

        float s1 = 0.f, s2 = 0.f;
#pragma unroll
        for (int t = 0; t < 4; t++) {
            int idx = lane + t * 32;
            float4 v = row[idx];
            float4 a = __ldg(&w1[idx]);
            float4 w = __ldg(&w2[idx]);
            s1 += v.x * a.x + v.y * a.y + v.z * a.z + v.w * a.w;
            s2 += v.x * w.x + v.y * w.y + v.z * w.z + v.w * w.w;
        }
#pragma unroll
        for (int o = 16; o; o >>= 1) {
            s1 += __shfl_xor_sync(0xffffffffu, s1, o);
            s2 += __shfl_xor_sync(0xffffffffu, s2, o);
        }
        if (lane == 0) { g_ei[r] = s1; g_ej[r] = s2; }
    } else {
        // zero output row (store stream overlaps the read stream)
        float4* orow4 = reinterpret_cast<float4*>(out + (size_t)r * L_DIM);
        float4 z = make_float4(0.f, 0.f, 0.f, 0.f);
#pragma unroll
        for (int t = 0; t < 4; t++) orow4[t * 32 + lane] = z;
    }
}

// ---------------- kernel 2: warp-autonomous masked softmax ----------------
// grid (L/32, B), block 256: warp w handles rows bx*32 + w*4 .. +3.
__global__ void __launch_bounds__(256) k_soft(const float* __restrict__ ba,
                                              const int* __restrict__ tlen,
                                              float* __restrict__ out) {
    const int b    = blockIdx.y;
    const int tid  = threadIdx.x;
    const int warp = tid >> 5;
    const int lane = tid & 31;
    const int len  = __ldg(&tlen[b]);            // input only: no dependency

    // whole CTA invalid: zeros already written by k_proj
    if ((int)blockIdx.x * 32 >= len) return;

    cudaGridDependencySynchronize();

    const int   nt = (len + 127) >> 7;           // live tiles (1..4), uniform
    const float4* ej4 = reinterpret_cast<const float4*>(g_ej + b * L_DIM);

    // all 512 premasked e_j in registers (4 coalesced LDG.128)
    float4 e[4];
    float mv = MASKV;
#pragma unroll
    for (int t = 0; t < 4; t++) {
        const int j0 = t * 128 + lane * 4;
        if (t < nt) {
            float4 v = __ldg(&ej4[t * 32 + lane]);
            const int rem = len - j0;
            v.x = (0 < rem) ? v.x : MASKV;
            v.y = (1 < rem) ? v.y : MASKV;
            v.z = (2 < rem) ? v.z : MASKV;
            v.w = (3 < rem) ? v.w : MASKV;
            e[t] = v;
            mv = fmaxf(mv, fmaxf(fmaxf(v.x, v.y), fmaxf(v.z, v.w)));
        } else {
            e[t] = make_float4(MASKV, MASKV, MASKV, MASKV);
        }
    }
#pragma unroll
    for (int o = 16; o; o >>= 1) mv = fmaxf(mv, __shfl_xor_sync(0xffffffffu, mv, o));
    const float mxej = mv;                        // batch max of premasked e_j

    const float bias = __ldg(ba);
    const int row0 = blockIdx.x * 32 + warp * 4;

#pragma unroll
    for (int rr = 0; rr < 4; rr++) {
        const int i = row0 + rr;
        if (i >= len) break;                      // zero rows written by k_proj

        float4* orow4 = reinterpret_cast<float4*>(out + ((size_t)b * L_DIM + i) * L_DIM);

        const float ei   = __ldg(&g_ei[b * L_DIM + i]) + bias;
        const float mraw = ei + mxej;
        const float m    = fmaxf(mraw, SLOPE * mraw);   // exact row max

        float4 p[4];
        float s = 0.f;
#pragma unroll
        for (int t = 0; t < 4; t++) {
            if (t < nt) {
                float v, lr, pe;
                v = ei + e[t].x; lr = fmaxf(v, SLOPE * v);
                pe = __expf(lr - m); p[t].x = pe; s += pe;
                v = ei + e[t].y; lr = fmaxf(v, SLOPE * v);
                pe = __expf(lr - m); p[t].y = pe; s += pe;
                v = ei + e[t].z; lr = fmaxf(v, SLOPE * v);
                pe = __expf(lr - m); p[t].z = pe; s += pe;
                v = ei + e[t].w; lr = fmaxf(v, SLOPE * v);
                pe = __expf(lr - m); p[t].w = pe; s += pe;
            }
        }
#pragma unroll
        for (int o = 16; o; o >>= 1) s += __shfl_xor_sync(0xffffffffu, s, o);

        const float inv = 1.f / s;
#pragma unroll
        for (int t = 0; t < 4; t++) {
            float4 r;
            if (t < nt) {
                r.x = p[t].x * inv; r.y = p[t].y * inv;
                r.z = p[t].z * inv; r.w = p[t].w * inv;
            } else {
                r = make_float4(0.f, 0.f, 0.f, 0.f);
            }
            orow4[t * 32 + lane] = r;
        }
    }
}

extern "C" void kernel_launch(void* const* d_in, const int* in_sizes, int n_in,
                              void* d_out, int out_size) {
    const float* nf   = (const float*)d_in[0];   // [B, L, D]
    const float* wa   = (const float*)d_in[1];   // [2D]
    const float* ba   = (const float*)d_in[2];   // [1]
    const int*   tlen = (const int*)d_in[3];     // [B]
    float* out = (float*)d_out;                  // [B, L, L]

    const int B = in_sizes[3];

    k_proj<<<B * L_DIM / 8, 256>>>(nf, wa, tlen, out);

    cudaLaunchConfig_t cfg = {};
    cfg.gridDim  = dim3(L_DIM / 32, (unsigned)B, 1);
    cfg.blockDim = dim3(256, 1, 1);
    cfg.dynamicSmemBytes = 0;
    cfg.stream = 0;
    cudaLaunchAttribute attr[1];
    attr[0].id = cudaLaunchAttributeProgrammaticStreamSerialization;
    attr[0].val.programmaticStreamSerializationAllowed = 1;
    cfg.attrs = attr;
    cfg.numAttrs = 1;
    cudaLaunchKernelEx(&cfg, k_soft, ba, tlen, out);
}